// round 12
// baseline (speedup 1.0000x reference)
#include <cuda_runtime.h>
#include <math.h>

#define BATCH   8
#define NPTS    8192
#define NPOINT  2048
#define NSAMPLE 32
#define FULLM   0xffffffffu
#define NCHUNKS (BATCH * NPOINT / 8)
#define FUSED_BLOCKS 140

// ---------------- device scratch (no allocs allowed) ----------------
__device__ float g_W1t[3 * 64];
__device__ float g_W2t[64 * 64];
__device__ float g_W3t[64 * 128];
__device__ float g_B[256];
__device__ int   g_progress[BATCH];
__device__ unsigned g_ctr;

// ---------------- prep: fold BN into weights + reset sync state ----------------
__global__ void prep_kernel(
    const float* __restrict__ w1, const float* __restrict__ b1, const float* __restrict__ g1,
    const float* __restrict__ be1, const float* __restrict__ m1, const float* __restrict__ v1,
    const float* __restrict__ w2, const float* __restrict__ b2, const float* __restrict__ g2,
    const float* __restrict__ be2, const float* __restrict__ m2, const float* __restrict__ v2,
    const float* __restrict__ w3, const float* __restrict__ b3, const float* __restrict__ g3,
    const float* __restrict__ be3, const float* __restrict__ m3, const float* __restrict__ v3)
{
    int t = threadIdx.x;
    if (t < BATCH) g_progress[t] = 0;
    if (t == 0) g_ctr = 0;
    if (t < 64) {
        float s1 = g1[t] / sqrtf(v1[t] + 1e-5f);
        g_B[t] = (b1[t] - m1[t]) * s1 + be1[t];
        for (int c = 0; c < 3; c++) g_W1t[c * 64 + t] = w1[t * 3 + c] * s1;
        float s2 = g2[t] / sqrtf(v2[t] + 1e-5f);
        g_B[64 + t] = (b2[t] - m2[t]) * s2 + be2[t];
        for (int c = 0; c < 64; c++) g_W2t[c * 64 + t] = w2[t * 64 + c] * s2;
    }
    if (t < 128) {
        float s3 = g3[t] / sqrtf(v3[t] + 1e-5f);
        g_B[128 + t] = (b3[t] - m3[t]) * s3 + be3[t];
        for (int c = 0; c < 64; c++) g_W3t[c * 128 + t] = w3[t * 64 + c] * s3;
    }
}

// ---------------- FPS: Morton-sorted, two-level (warp+thread) lazy skip ----------------
extern __shared__ float fps_sm[];

__device__ __forceinline__ unsigned spread3(unsigned v) {
    v = (v | (v << 4)) & 0x0C3u;
    v = (v | (v << 2)) & 0x249u;
    return v;
}

__global__ __launch_bounds__(1024, 1) void fps_kernel(
    const float* __restrict__ xyz, float* __restrict__ newxyz)
{
    const int b = blockIdx.x;
    const float* P = xyz + (size_t)b * NPTS * 3;
    float* O = newxyz + (size_t)b * NPOINT * 3;
    const int tid = threadIdx.x;
    const int lane = tid & 31, wid = tid >> 5;

    float4* shc = (float4*)fps_sm;          // [8192] coords by original index
    int*    hist  = (int*)(shc + NPTS);     // [4096]
    int*    order = hist + 4096;            // [8192]

    __shared__ unsigned svv[2][32];
    __shared__ unsigned sii[2][32];
    __shared__ int wsums[32];

    for (int i = tid; i < 4096; i += 1024) hist[i] = 0;
    __syncthreads();
    unsigned key[8];
#pragma unroll
    for (int k = 0; k < 8; k++) {
        int p = tid + 1024 * k;
        float x = P[3 * p], y = P[3 * p + 1], z = P[3 * p + 2];
        shc[p] = make_float4(x, y, z, 0.0f);
        int ix = min(15, max(0, (int)(x * 16.0f)));
        int iy = min(15, max(0, (int)(y * 16.0f)));
        int iz = min(15, max(0, (int)(z * 16.0f)));
        key[k] = spread3((unsigned)ix) | (spread3((unsigned)iy) << 1) | (spread3((unsigned)iz) << 2);
        atomicAdd(&hist[key[k]], 1);
    }
    __syncthreads();

    int h0 = hist[4 * tid], h1 = hist[4 * tid + 1], h2 = hist[4 * tid + 2], h3 = hist[4 * tid + 3];
    int tsum = h0 + h1 + h2 + h3;
    int inc = tsum;
#pragma unroll
    for (int off = 1; off < 32; off <<= 1) {
        int n = __shfl_up_sync(FULLM, inc, off);
        if (lane >= off) inc += n;
    }
    if (lane == 31) wsums[wid] = inc;
    __syncthreads();
    if (wid == 0) {
        int s = wsums[lane];
        int i2 = s;
#pragma unroll
        for (int off = 1; off < 32; off <<= 1) {
            int n = __shfl_up_sync(FULLM, i2, off);
            if (lane >= off) i2 += n;
        }
        wsums[lane] = i2 - s;
    }
    __syncthreads();
    {
        int run = wsums[wid] + (inc - tsum);
        hist[4 * tid] = run; run += h0;
        hist[4 * tid + 1] = run; run += h1;
        hist[4 * tid + 2] = run; run += h2;
        hist[4 * tid + 3] = run;
    }
    __syncthreads();

#pragma unroll
    for (int k = 0; k < 8; k++) {
        int pos = atomicAdd(&hist[key[k]], 1);
        order[pos] = tid + 1024 * k;
    }
    __syncthreads();

    float cx = P[0], cy = P[1], cz = P[2];
    if (tid == 0) { O[0] = cx; O[1] = cy; O[2] = cz; }

    int   orig[8];
    float px[8], py[8], pz[8], d[8];
    float bxl = 1e30f, bxh = -1e30f, byl = 1e30f, byh = -1e30f, bzl = 1e30f, bzh = -1e30f;
#pragma unroll
    for (int j = 0; j < 8; j++) {
        int o = order[8 * tid + j];
        orig[j] = o;
        float4 c4 = shc[o];
        float x = c4.x, y = c4.y, z = c4.z;
        px[j] = x; py[j] = y; pz[j] = z;
        bxl = fminf(bxl, x); bxh = fmaxf(bxh, x);
        byl = fminf(byl, y); byh = fmaxf(byh, y);
        bzl = fminf(bzl, z); bzh = fmaxf(bzh, z);
        float dx = __fadd_rn(x, -cx), dy = __fadd_rn(y, -cy), dz = __fadd_rn(z, -cz);
        d[j] = __fadd_rn(__fadd_rn(__fmul_rn(dx, dx), __fmul_rn(dy, dy)), __fmul_rn(dz, dz));
    }
    const float bcx = (bxl + bxh) * 0.5f, bex = (bxh - bxl) * 0.5f;
    const float bcy = (byl + byh) * 0.5f, bey = (byh - byl) * 0.5f;
    const float bcz = (bzl + bzh) * 0.5f, bez = (bzh - bzl) * 0.5f;

    // warp bbox (register-replicated; coords >= 0 so uint order == float order)
    const float Wxl = __uint_as_float(__reduce_min_sync(FULLM, __float_as_uint(bxl)));
    const float Wxh = __uint_as_float(__reduce_max_sync(FULLM, __float_as_uint(bxh)));
    const float Wyl = __uint_as_float(__reduce_min_sync(FULLM, __float_as_uint(byl)));
    const float Wyh = __uint_as_float(__reduce_max_sync(FULLM, __float_as_uint(byh)));
    const float Wzl = __uint_as_float(__reduce_min_sync(FULLM, __float_as_uint(bzl)));
    const float Wzh = __uint_as_float(__reduce_max_sync(FULLM, __float_as_uint(bzh)));
    const float Wcx = (Wxl + Wxh) * 0.5f, Wex = (Wxh - Wxl) * 0.5f;
    const float Wcy = (Wyl + Wyh) * 0.5f, Wey = (Wyh - Wyl) * 0.5f;
    const float Wcz = (Wzl + Wzh) * 0.5f, Wez = (Wzh - Wzl) * 0.5f;

    // per-thread cached argmax
    float vmax; unsigned bidx;
    {
        float v = d[0];
#pragma unroll
        for (int j = 1; j < 8; j++) v = fmaxf(v, d[j]);
        unsigned bi = FULLM;
#pragma unroll
        for (int j = 0; j < 8; j++) if (d[j] == v) bi = min(bi, (unsigned)orig[j]);
        vmax = v; bidx = bi;
    }
    // warp cached result (register-replicated)
    float wvmax; unsigned wbi;
    {
        unsigned wm = __reduce_max_sync(FULLM, __float_as_uint(vmax));
        unsigned cd = (__float_as_uint(vmax) == wm) ? bidx : FULLM;
        wbi = __reduce_min_sync(FULLM, cd);
        wvmax = __uint_as_float(wm);
    }

    for (int it = 1; it < NPOINT; ++it) {
        const int par = it & 1;

        // ---- warp-level conservative skip (identical across lanes) ----
        float wtx = fmaxf(fabsf(cx - Wcx) - Wex, 0.0f);
        float wty = fmaxf(fabsf(cy - Wcy) - Wey, 0.0f);
        float wtz = fmaxf(fabsf(cz - Wcz) - Wez, 0.0f);
        float wbound = wtx * wtx + wty * wty + wtz * wtz;
        if (wbound < wvmax * 1.0002f) {
            // ---- thread-level test + update (R8 path, byte-identical) ----
            float tx = fmaxf(fabsf(cx - bcx) - bex, 0.0f);
            float ty = fmaxf(fabsf(cy - bcy) - bey, 0.0f);
            float tz = fmaxf(fabsf(cz - bcz) - bez, 0.0f);
            float bound = tx * tx + ty * ty + tz * tz;
            if (bound < vmax * 1.0002f) {
#pragma unroll
                for (int j = 0; j < 8; j++) {
                    float dx = __fadd_rn(px[j], -cx);
                    float dy = __fadd_rn(py[j], -cy);
                    float dz = __fadd_rn(pz[j], -cz);
                    float s = __fadd_rn(__fadd_rn(__fmul_rn(dx, dx), __fmul_rn(dy, dy)),
                                        __fmul_rn(dz, dz));
                    d[j] = fminf(d[j], s);
                }
                float v = d[0];
#pragma unroll
                for (int j = 1; j < 8; j++) v = fmaxf(v, d[j]);
                unsigned bi = FULLM;
#pragma unroll
                for (int j = 0; j < 8; j++) if (d[j] == v) bi = min(bi, (unsigned)orig[j]);
                vmax = v; bidx = bi;
            }
            // refresh warp cached result
            unsigned keyv = __float_as_uint(vmax);
            unsigned wm = __reduce_max_sync(FULLM, keyv);
            unsigned cd = (keyv == wm) ? bidx : FULLM;
            wbi = __reduce_min_sync(FULLM, cd);
            wvmax = __uint_as_float(wm);
        }
        if (lane == 0) { svv[par][wid] = __float_as_uint(wvmax); sii[par][wid] = wbi; }
        __syncthreads();

        // ---- block combine (every warp redundantly) ----
        unsigned k2 = svv[par][lane];
        unsigned i2 = sii[par][lane];
        unsigned m2 = __reduce_max_sync(FULLM, k2);
        unsigned c2 = (k2 == m2) ? i2 : FULLM;
        unsigned ci = __reduce_min_sync(FULLM, c2);

        float4 c4 = shc[ci];                 // one LDS.128, broadcast
        cx = c4.x; cy = c4.y; cz = c4.z;
        if (tid == 0) {
            float* o = O + 3 * it; o[0] = cx; o[1] = cy; o[2] = cz;
            if ((it & 7) == 7) {
                __threadfence();
                *((volatile int*)&g_progress[b]) = it + 1;
            }
        }
    }
}

// ---------------- persistent fused consumer (unchanged from R10) ----------------
extern __shared__ float fus_sm[];

__global__ __launch_bounds__(256) void fused_kernel(
    const float* __restrict__ xyz, const float* __restrict__ newxyz,
    float* __restrict__ out2)
{
    float* W2t   = fus_sm;
    float* W3t   = W2t + 64 * 64;
    float* W1t   = W3t + 64 * 128;
    float* Bsh   = W1t + 192;
    float* stage = Bsh + 256;
    int*   nb    = (int*)(stage + 128 * 8);

    const int tid = threadIdx.x;
    for (int i = tid; i < 64 * 64; i += 256)  W2t[i] = g_W2t[i];
    for (int i = tid; i < 64 * 128; i += 256) W3t[i] = g_W3t[i];
    if (tid < 192) W1t[tid] = g_W1t[tid];
    if (tid < 256) Bsh[tid] = g_B[tid];

    const int w = tid >> 5, lane = tid & 31;
    __shared__ int sh_c;

    for (;;) {
        __syncthreads();
        if (tid == 0) sh_c = (int)atomicAdd(&g_ctr, 1u);
        __syncthreads();
        const int c = sh_c;
        if (c >= NCHUNKS) break;

        const int b  = c & 7;
        const int m0 = (c >> 3) << 3;
        const int m  = m0 + w;

        if (tid == 0) {
            while (*((volatile int*)&g_progress[b]) < m0 + 8) __nanosleep(128);
        }
        __syncthreads();
        __threadfence();

        const float* P = xyz + (size_t)b * NPTS * 3;
        const float* C = newxyz + ((size_t)b * NPOINT + m) * 3;
        const float cx = __ldcg(C), cy = __ldcg(C + 1), cz = __ldcg(C + 2);

        const float R2 = (float)(0.2 * 0.2);
        int* mynb = nb + w * 32;
        int cnt = 0;
        for (int base = 0; base < NPTS && cnt < NSAMPLE; base += 32) {
            int p = base + lane;
            float x = P[3 * p], y = P[3 * p + 1], z = P[3 * p + 2];
            float dx = __fadd_rn(x, -cx), dy = __fadd_rn(y, -cy), dz = __fadd_rn(z, -cz);
            float s = __fadd_rn(__fadd_rn(__fmul_rn(dx, dx), __fmul_rn(dy, dy)), __fmul_rn(dz, dz));
            bool in = (s <= R2);
            unsigned msk = __ballot_sync(FULLM, in);
            int pos = cnt + __popc(msk & ((1u << lane) - 1u));
            if (in && pos < NSAMPLE) mynb[pos] = p;
            cnt += __popc(msk);
        }
        __syncwarp();
        int src = (cnt >= NSAMPLE) ? lane : (lane % cnt);
        int gidx = mynb[src];

        float gx = P[3 * gidx] - cx, gy = P[3 * gidx + 1] - cy, gz = P[3 * gidx + 2] - cz;

        float h1[64];
#pragma unroll
        for (int o = 0; o < 64; o++) h1[o] = fmaf(gx, W1t[o], Bsh[o]);
#pragma unroll
        for (int o = 0; o < 64; o++) h1[o] = fmaf(gy, W1t[64 + o], h1[o]);
#pragma unroll
        for (int o = 0; o < 64; o++) h1[o] = fmaxf(fmaf(gz, W1t[128 + o], h1[o]), 0.0f);

        float h2[64];
#pragma unroll
        for (int o = 0; o < 64; o++) h2[o] = Bsh[64 + o];
#pragma unroll
        for (int cc = 0; cc < 64; cc++) {
            float hc = h1[cc];
            const float4* wr = (const float4*)(W2t + cc * 64);
#pragma unroll
            for (int q = 0; q < 16; q++) {
                float4 wv = wr[q];
                h2[4 * q + 0] = fmaf(hc, wv.x, h2[4 * q + 0]);
                h2[4 * q + 1] = fmaf(hc, wv.y, h2[4 * q + 1]);
                h2[4 * q + 2] = fmaf(hc, wv.z, h2[4 * q + 2]);
                h2[4 * q + 3] = fmaf(hc, wv.w, h2[4 * q + 3]);
            }
        }
#pragma unroll
        for (int o = 0; o < 64; o++) h2[o] = fmaxf(h2[o], 0.0f);

#pragma unroll
        for (int half = 0; half < 2; half++) {
            float acc[64];
#pragma unroll
            for (int o = 0; o < 64; o++) acc[o] = Bsh[128 + half * 64 + o];
#pragma unroll
            for (int cc = 0; cc < 64; cc++) {
                float hc = h2[cc];
                const float4* wr = (const float4*)(W3t + cc * 128 + half * 64);
#pragma unroll
                for (int q = 0; q < 16; q++) {
                    float4 wv = wr[q];
                    acc[4 * q + 0] = fmaf(hc, wv.x, acc[4 * q + 0]);
                    acc[4 * q + 1] = fmaf(hc, wv.y, acc[4 * q + 1]);
                    acc[4 * q + 2] = fmaf(hc, wv.z, acc[4 * q + 2]);
                    acc[4 * q + 3] = fmaf(hc, wv.w, acc[4 * q + 3]);
                }
            }
#pragma unroll
            for (int o = 0; o < 64; o++) acc[o] = fmaxf(acc[o], 0.0f);
#pragma unroll
            for (int off = 16; off >= 1; off >>= 1) {
#pragma unroll
                for (int o = 0; o < 64; o++)
                    acc[o] = fmaxf(acc[o], __shfl_down_sync(FULLM, acc[o], off));
            }
            if (lane == 0) {
#pragma unroll
                for (int o = 0; o < 64; o++) stage[(half * 64 + o) * 8 + w] = acc[o];
            }
        }
        __syncthreads();

        {
            int ch = tid >> 1, part = tid & 1;
            float4 v = ((const float4*)stage)[tid];
            *(float4*)(out2 + ((size_t)(b * 128 + ch)) * NPOINT + m0 + part * 4) = v;
        }
    }
}

// ---------------- launch: prep -> fork {FPS, fused} -> join ----------------
extern "C" void kernel_launch(void* const* d_in, const int* in_sizes, int n_in,
                              void* d_out, int out_size)
{
    const float* xyz = (const float*)d_in[0];
    const float* w1 = (const float*)d_in[1];  const float* b1 = (const float*)d_in[2];
    const float* g1 = (const float*)d_in[3];  const float* be1 = (const float*)d_in[4];
    const float* m1 = (const float*)d_in[5];  const float* v1 = (const float*)d_in[6];
    const float* w2 = (const float*)d_in[7];  const float* b2 = (const float*)d_in[8];
    const float* g2 = (const float*)d_in[9];  const float* be2 = (const float*)d_in[10];
    const float* m2 = (const float*)d_in[11]; const float* v2 = (const float*)d_in[12];
    const float* w3 = (const float*)d_in[13]; const float* b3 = (const float*)d_in[14];
    const float* g3 = (const float*)d_in[15]; const float* be3 = (const float*)d_in[16];
    const float* m3 = (const float*)d_in[17]; const float* v3 = (const float*)d_in[18];

    float* out = (float*)d_out;
    float* newxyz = out;
    float* out2 = out + (size_t)BATCH * NPOINT * 3;

    static cudaStream_t s_aux = nullptr;
    static cudaEvent_t e_fork = nullptr, e_join = nullptr;
    if (s_aux == nullptr) {
        cudaStreamCreateWithFlags(&s_aux, cudaStreamNonBlocking);
        cudaEventCreateWithFlags(&e_fork, cudaEventDisableTiming);
        cudaEventCreateWithFlags(&e_join, cudaEventDisableTiming);
    }

    const int FPS_SMEM = NPTS * 16 + 4096 * 4 + NPTS * 4;   // 180224
    cudaFuncSetAttribute(fps_kernel, cudaFuncAttributeMaxDynamicSharedMemorySize, FPS_SMEM);
    cudaFuncSetAttribute(fused_kernel, cudaFuncAttributeMaxDynamicSharedMemorySize, 57344);

    prep_kernel<<<1, 128>>>(w1, b1, g1, be1, m1, v1,
                            w2, b2, g2, be2, m2, v2,
                            w3, b3, g3, be3, m3, v3);

    cudaEventRecord(e_fork, 0);
    cudaStreamWaitEvent(s_aux, e_fork, 0);

    fps_kernel<<<BATCH, 1024, FPS_SMEM>>>(xyz, newxyz);
    fused_kernel<<<FUSED_BLOCKS, 256, 56064, s_aux>>>(xyz, newxyz, out2);

    cudaEventRecord(e_join, s_aux);
    cudaStreamWaitEvent(0, e_join, 0);
    (void)in_sizes; (void)n_in; (void)out_size;
}

// round 13
// speedup vs baseline: 1.0070x; 1.0070x over previous
#include <cuda_runtime.h>
#include <math.h>

#define BATCH   8
#define NPTS    8192
#define NPOINT  2048
#define NSAMPLE 32
#define FULLM   0xffffffffu
#define NCHUNKS (BATCH * NPOINT / 8)
#define FUSED_BLOCKS 140

// ---------------- device scratch (no allocs allowed) ----------------
__device__ float g_W1t[3 * 64];
__device__ float g_W2t[64 * 64];
__device__ float g_W3t[64 * 128];
__device__ float g_B[256];
__device__ int   g_progress[BATCH];
__device__ unsigned g_ctr;

// ---------------- prep: fold BN into weights + reset sync state ----------------
__global__ void prep_kernel(
    const float* __restrict__ w1, const float* __restrict__ b1, const float* __restrict__ g1,
    const float* __restrict__ be1, const float* __restrict__ m1, const float* __restrict__ v1,
    const float* __restrict__ w2, const float* __restrict__ b2, const float* __restrict__ g2,
    const float* __restrict__ be2, const float* __restrict__ m2, const float* __restrict__ v2,
    const float* __restrict__ w3, const float* __restrict__ b3, const float* __restrict__ g3,
    const float* __restrict__ be3, const float* __restrict__ m3, const float* __restrict__ v3)
{
    int t = threadIdx.x;
    if (t < BATCH) g_progress[t] = 0;
    if (t == 0) g_ctr = 0;
    if (t < 64) {
        float s1 = g1[t] / sqrtf(v1[t] + 1e-5f);
        g_B[t] = (b1[t] - m1[t]) * s1 + be1[t];
        for (int c = 0; c < 3; c++) g_W1t[c * 64 + t] = w1[t * 3 + c] * s1;
        float s2 = g2[t] / sqrtf(v2[t] + 1e-5f);
        g_B[64 + t] = (b2[t] - m2[t]) * s2 + be2[t];
        for (int c = 0; c < 64; c++) g_W2t[c * 64 + t] = w2[t * 64 + c] * s2;
    }
    if (t < 128) {
        float s3 = g3[t] / sqrtf(v3[t] + 1e-5f);
        g_B[128 + t] = (b3[t] - m3[t]) * s3 + be3[t];
        for (int c = 0; c < 64; c++) g_W3t[c * 128 + t] = w3[t * 64 + c] * s3;
    }
}

// ---------------- FPS: Morton-sorted lazy; minimal every-warp path ----------------
extern __shared__ float fps_sm[];

__device__ __forceinline__ unsigned spread3(unsigned v) {
    v = (v | (v << 4)) & 0x0C3u;
    v = (v | (v << 2)) & 0x249u;
    return v;
}

__global__ __launch_bounds__(1024, 1) void fps_kernel(
    const float* __restrict__ xyz, float* __restrict__ newxyz)
{
    const int b = blockIdx.x;
    const float* P = xyz + (size_t)b * NPTS * 3;
    float* O = newxyz + (size_t)b * NPOINT * 3;
    const int tid = threadIdx.x;
    const int lane = tid & 31, wid = tid >> 5;

    float4* shc = (float4*)fps_sm;          // [8192] coords by original index
    int*    hist  = (int*)(shc + NPTS);     // [4096]
    int*    order = hist + 4096;            // [8192]

    __shared__ unsigned svv[32];            // persistent per-warp max (exact)
    __shared__ unsigned sii[32];            // persistent per-warp tie-min orig idx
    __shared__ float4 s_pick;
    __shared__ int wsums[32];

    for (int i = tid; i < 4096; i += 1024) hist[i] = 0;
    __syncthreads();
    unsigned key[8];
#pragma unroll
    for (int k = 0; k < 8; k++) {
        int p = tid + 1024 * k;
        float x = P[3 * p], y = P[3 * p + 1], z = P[3 * p + 2];
        shc[p] = make_float4(x, y, z, 0.0f);
        int ix = min(15, max(0, (int)(x * 16.0f)));
        int iy = min(15, max(0, (int)(y * 16.0f)));
        int iz = min(15, max(0, (int)(z * 16.0f)));
        key[k] = spread3((unsigned)ix) | (spread3((unsigned)iy) << 1) | (spread3((unsigned)iz) << 2);
        atomicAdd(&hist[key[k]], 1);
    }
    __syncthreads();

    int h0 = hist[4 * tid], h1 = hist[4 * tid + 1], h2 = hist[4 * tid + 2], h3 = hist[4 * tid + 3];
    int tsum = h0 + h1 + h2 + h3;
    int inc = tsum;
#pragma unroll
    for (int off = 1; off < 32; off <<= 1) {
        int n = __shfl_up_sync(FULLM, inc, off);
        if (lane >= off) inc += n;
    }
    if (lane == 31) wsums[wid] = inc;
    __syncthreads();
    if (wid == 0) {
        int s = wsums[lane];
        int i2 = s;
#pragma unroll
        for (int off = 1; off < 32; off <<= 1) {
            int n = __shfl_up_sync(FULLM, i2, off);
            if (lane >= off) i2 += n;
        }
        wsums[lane] = i2 - s;
    }
    __syncthreads();
    {
        int run = wsums[wid] + (inc - tsum);
        hist[4 * tid] = run; run += h0;
        hist[4 * tid + 1] = run; run += h1;
        hist[4 * tid + 2] = run; run += h2;
        hist[4 * tid + 3] = run;
    }
    __syncthreads();

#pragma unroll
    for (int k = 0; k < 8; k++) {
        int pos = atomicAdd(&hist[key[k]], 1);
        order[pos] = tid + 1024 * k;
    }
    __syncthreads();

    float cx = P[0], cy = P[1], cz = P[2];
    if (tid == 0) { O[0] = cx; O[1] = cy; O[2] = cz; }

    int   orig[8];
    float px[8], py[8], pz[8], d[8];
    float bxl = 1e30f, bxh = -1e30f, byl = 1e30f, byh = -1e30f, bzl = 1e30f, bzh = -1e30f;
#pragma unroll
    for (int j = 0; j < 8; j++) {
        int o = order[8 * tid + j];
        orig[j] = o;
        float4 c4 = shc[o];
        float x = c4.x, y = c4.y, z = c4.z;
        px[j] = x; py[j] = y; pz[j] = z;
        bxl = fminf(bxl, x); bxh = fmaxf(bxh, x);
        byl = fminf(byl, y); byh = fmaxf(byh, y);
        bzl = fminf(bzl, z); bzh = fmaxf(bzh, z);
        float dx = __fadd_rn(x, -cx), dy = __fadd_rn(y, -cy), dz = __fadd_rn(z, -cz);
        d[j] = __fadd_rn(__fadd_rn(__fmul_rn(dx, dx), __fmul_rn(dy, dy)), __fmul_rn(dz, dz));
    }
    const float bcx = (bxl + bxh) * 0.5f, bex = (bxh - bxl) * 0.5f;
    const float bcy = (byl + byh) * 0.5f, bey = (byh - byl) * 0.5f;
    const float bcz = (bzl + bzh) * 0.5f, bez = (bzh - bzl) * 0.5f;

    // cached per-thread argmax
    float vmax; unsigned bidx;
    {
        float v = d[0];
#pragma unroll
        for (int j = 1; j < 8; j++) v = fmaxf(v, d[j]);
        unsigned bi = FULLM;
#pragma unroll
        for (int j = 0; j < 8; j++) if (d[j] == v) bi = min(bi, (unsigned)orig[j]);
        vmax = v; bidx = bi;
    }
    // initial per-warp store
    {
        unsigned keyv = __float_as_uint(vmax);
        unsigned wm = __reduce_max_sync(FULLM, keyv);
        unsigned cd = (keyv == wm) ? bidx : FULLM;
        unsigned wi = __reduce_min_sync(FULLM, cd);
        if (lane == 0) { svv[wid] = wm; sii[wid] = wi; }
    }

    for (int it = 1; it < NPOINT; ++it) {
        // ---- thread-level conservative skip + exact update ----
        float tx = fmaxf(fabsf(cx - bcx) - bex, 0.0f);
        float ty = fmaxf(fabsf(cy - bcy) - bey, 0.0f);
        float tz = fmaxf(fabsf(cz - bcz) - bez, 0.0f);
        float bound = tx * tx + ty * ty + tz * tz;
        bool upd = bound < vmax * 1.0002f;
        if (upd) {
#pragma unroll
            for (int j = 0; j < 8; j++) {
                float dx = __fadd_rn(px[j], -cx);
                float dy = __fadd_rn(py[j], -cy);
                float dz = __fadd_rn(pz[j], -cz);
                float s = __fadd_rn(__fadd_rn(__fmul_rn(dx, dx), __fmul_rn(dy, dy)),
                                    __fmul_rn(dz, dz));
                d[j] = fminf(d[j], s);
            }
            float v = d[0];
#pragma unroll
            for (int j = 1; j < 8; j++) v = fmaxf(v, d[j]);
            unsigned bi = FULLM;
#pragma unroll
            for (int j = 0; j < 8; j++) if (d[j] == v) bi = min(bi, (unsigned)orig[j]);
            vmax = v; bidx = bi;
        }
        // refresh this warp's stored result only if some lane changed
        if (__ballot_sync(FULLM, upd)) {
            unsigned keyv = __float_as_uint(vmax);
            unsigned wm = __reduce_max_sync(FULLM, keyv);
            unsigned cd = (keyv == wm) ? bidx : FULLM;
            unsigned wi = __reduce_min_sync(FULLM, cd);
            if (lane == 0) { svv[wid] = wm; sii[wid] = wi; }
        }
        __syncthreads();                         // stores visible to warp 0

        if (wid == 0) {                          // combine + publish (warp 0 only)
            unsigned k2 = svv[lane];
            unsigned i2 = sii[lane];
            unsigned m2 = __reduce_max_sync(FULLM, k2);
            unsigned c2 = (k2 == m2) ? i2 : FULLM;
            unsigned ci = __reduce_min_sync(FULLM, c2);
            float4 c4 = shc[ci];
            if (lane == 0) {
                s_pick = c4;
                float* o = O + 3 * it; o[0] = c4.x; o[1] = c4.y; o[2] = c4.z;
                if ((it & 7) == 7) {
                    __threadfence();
                    *((volatile int*)&g_progress[b]) = it + 1;
                }
            }
        }
        __syncthreads();                         // pick published

        float4 c4 = s_pick;
        cx = c4.x; cy = c4.y; cz = c4.z;
    }
}

// ---------------- persistent fused consumer (unchanged) ----------------
extern __shared__ float fus_sm[];

__global__ __launch_bounds__(256) void fused_kernel(
    const float* __restrict__ xyz, const float* __restrict__ newxyz,
    float* __restrict__ out2)
{
    float* W2t   = fus_sm;
    float* W3t   = W2t + 64 * 64;
    float* W1t   = W3t + 64 * 128;
    float* Bsh   = W1t + 192;
    float* stage = Bsh + 256;
    int*   nb    = (int*)(stage + 128 * 8);

    const int tid = threadIdx.x;
    for (int i = tid; i < 64 * 64; i += 256)  W2t[i] = g_W2t[i];
    for (int i = tid; i < 64 * 128; i += 256) W3t[i] = g_W3t[i];
    if (tid < 192) W1t[tid] = g_W1t[tid];
    if (tid < 256) Bsh[tid] = g_B[tid];

    const int w = tid >> 5, lane = tid & 31;
    __shared__ int sh_c;

    for (;;) {
        __syncthreads();
        if (tid == 0) sh_c = (int)atomicAdd(&g_ctr, 1u);
        __syncthreads();
        const int c = sh_c;
        if (c >= NCHUNKS) break;

        const int b  = c & 7;
        const int m0 = (c >> 3) << 3;
        const int m  = m0 + w;

        if (tid == 0) {
            while (*((volatile int*)&g_progress[b]) < m0 + 8) __nanosleep(128);
        }
        __syncthreads();
        __threadfence();

        const float* P = xyz + (size_t)b * NPTS * 3;
        const float* C = newxyz + ((size_t)b * NPOINT + m) * 3;
        const float cx = __ldcg(C), cy = __ldcg(C + 1), cz = __ldcg(C + 2);

        const float R2 = (float)(0.2 * 0.2);
        int* mynb = nb + w * 32;
        int cnt = 0;
        for (int base = 0; base < NPTS && cnt < NSAMPLE; base += 32) {
            int p = base + lane;
            float x = P[3 * p], y = P[3 * p + 1], z = P[3 * p + 2];
            float dx = __fadd_rn(x, -cx), dy = __fadd_rn(y, -cy), dz = __fadd_rn(z, -cz);
            float s = __fadd_rn(__fadd_rn(__fmul_rn(dx, dx), __fmul_rn(dy, dy)), __fmul_rn(dz, dz));
            bool in = (s <= R2);
            unsigned msk = __ballot_sync(FULLM, in);
            int pos = cnt + __popc(msk & ((1u << lane) - 1u));
            if (in && pos < NSAMPLE) mynb[pos] = p;
            cnt += __popc(msk);
        }
        __syncwarp();
        int src = (cnt >= NSAMPLE) ? lane : (lane % cnt);
        int gidx = mynb[src];

        float gx = P[3 * gidx] - cx, gy = P[3 * gidx + 1] - cy, gz = P[3 * gidx + 2] - cz;

        float h1[64];
#pragma unroll
        for (int o = 0; o < 64; o++) h1[o] = fmaf(gx, W1t[o], Bsh[o]);
#pragma unroll
        for (int o = 0; o < 64; o++) h1[o] = fmaf(gy, W1t[64 + o], h1[o]);
#pragma unroll
        for (int o = 0; o < 64; o++) h1[o] = fmaxf(fmaf(gz, W1t[128 + o], h1[o]), 0.0f);

        float h2[64];
#pragma unroll
        for (int o = 0; o < 64; o++) h2[o] = Bsh[64 + o];
#pragma unroll
        for (int cc = 0; cc < 64; cc++) {
            float hc = h1[cc];
            const float4* wr = (const float4*)(W2t + cc * 64);
#pragma unroll
            for (int q = 0; q < 16; q++) {
                float4 wv = wr[q];
                h2[4 * q + 0] = fmaf(hc, wv.x, h2[4 * q + 0]);
                h2[4 * q + 1] = fmaf(hc, wv.y, h2[4 * q + 1]);
                h2[4 * q + 2] = fmaf(hc, wv.z, h2[4 * q + 2]);
                h2[4 * q + 3] = fmaf(hc, wv.w, h2[4 * q + 3]);
            }
        }
#pragma unroll
        for (int o = 0; o < 64; o++) h2[o] = fmaxf(h2[o], 0.0f);

#pragma unroll
        for (int half = 0; half < 2; half++) {
            float acc[64];
#pragma unroll
            for (int o = 0; o < 64; o++) acc[o] = Bsh[128 + half * 64 + o];
#pragma unroll
            for (int cc = 0; cc < 64; cc++) {
                float hc = h2[cc];
                const float4* wr = (const float4*)(W3t + cc * 128 + half * 64);
#pragma unroll
                for (int q = 0; q < 16; q++) {
                    float4 wv = wr[q];
                    acc[4 * q + 0] = fmaf(hc, wv.x, acc[4 * q + 0]);
                    acc[4 * q + 1] = fmaf(hc, wv.y, acc[4 * q + 1]);
                    acc[4 * q + 2] = fmaf(hc, wv.z, acc[4 * q + 2]);
                    acc[4 * q + 3] = fmaf(hc, wv.w, acc[4 * q + 3]);
                }
            }
#pragma unroll
            for (int o = 0; o < 64; o++) acc[o] = fmaxf(acc[o], 0.0f);
#pragma unroll
            for (int off = 16; off >= 1; off >>= 1) {
#pragma unroll
                for (int o = 0; o < 64; o++)
                    acc[o] = fmaxf(acc[o], __shfl_down_sync(FULLM, acc[o], off));
            }
            if (lane == 0) {
#pragma unroll
                for (int o = 0; o < 64; o++) stage[(half * 64 + o) * 8 + w] = acc[o];
            }
        }
        __syncthreads();

        {
            int ch = tid >> 1, part = tid & 1;
            float4 v = ((const float4*)stage)[tid];
            *(float4*)(out2 + ((size_t)(b * 128 + ch)) * NPOINT + m0 + part * 4) = v;
        }
    }
}

// ---------------- launch: prep -> fork {FPS, fused} -> join ----------------
extern "C" void kernel_launch(void* const* d_in, const int* in_sizes, int n_in,
                              void* d_out, int out_size)
{
    const float* xyz = (const float*)d_in[0];
    const float* w1 = (const float*)d_in[1];  const float* b1 = (const float*)d_in[2];
    const float* g1 = (const float*)d_in[3];  const float* be1 = (const float*)d_in[4];
    const float* m1 = (const float*)d_in[5];  const float* v1 = (const float*)d_in[6];
    const float* w2 = (const float*)d_in[7];  const float* b2 = (const float*)d_in[8];
    const float* g2 = (const float*)d_in[9];  const float* be2 = (const float*)d_in[10];
    const float* m2 = (const float*)d_in[11]; const float* v2 = (const float*)d_in[12];
    const float* w3 = (const float*)d_in[13]; const float* b3 = (const float*)d_in[14];
    const float* g3 = (const float*)d_in[15]; const float* be3 = (const float*)d_in[16];
    const float* m3 = (const float*)d_in[17]; const float* v3 = (const float*)d_in[18];

    float* out = (float*)d_out;
    float* newxyz = out;
    float* out2 = out + (size_t)BATCH * NPOINT * 3;

    static cudaStream_t s_aux = nullptr;
    static cudaEvent_t e_fork = nullptr, e_join = nullptr;
    if (s_aux == nullptr) {
        cudaStreamCreateWithFlags(&s_aux, cudaStreamNonBlocking);
        cudaEventCreateWithFlags(&e_fork, cudaEventDisableTiming);
        cudaEventCreateWithFlags(&e_join, cudaEventDisableTiming);
    }

    const int FPS_SMEM = NPTS * 16 + 4096 * 4 + NPTS * 4;   // 180224
    cudaFuncSetAttribute(fps_kernel, cudaFuncAttributeMaxDynamicSharedMemorySize, FPS_SMEM);
    cudaFuncSetAttribute(fused_kernel, cudaFuncAttributeMaxDynamicSharedMemorySize, 57344);

    prep_kernel<<<1, 128>>>(w1, b1, g1, be1, m1, v1,
                            w2, b2, g2, be2, m2, v2,
                            w3, b3, g3, be3, m3, v3);

    cudaEventRecord(e_fork, 0);
    cudaStreamWaitEvent(s_aux, e_fork, 0);

    fps_kernel<<<BATCH, 1024, FPS_SMEM>>>(xyz, newxyz);
    fused_kernel<<<FUSED_BLOCKS, 256, 56064, s_aux>>>(xyz, newxyz, out2);

    cudaEventRecord(e_join, s_aux);
    cudaStreamWaitEvent(0, e_join, 0);
    (void)in_sizes; (void)n_in; (void)out_size;
}

// round 15
// speedup vs baseline: 1.0136x; 1.0065x over previous
#include <cuda_runtime.h>
#include <math.h>

#define BATCH   8
#define NPTS    8192
#define NPOINT  2048
#define NSAMPLE 32
#define FULLM   0xffffffffu
#define NCHUNKS (BATCH * NPOINT / 8)
#define FUSED_BLOCKS 140

// ---------------- device scratch (no allocs allowed) ----------------
__device__ float g_W1t[3 * 64];
__device__ float g_W2t[64 * 64];
__device__ float g_W3t[64 * 128];
__device__ float g_B[256];
__device__ int   g_progress[BATCH];
__device__ unsigned g_ctr;

// ---------------- prep: fold BN into weights + reset sync state ----------------
__global__ void prep_kernel(
    const float* __restrict__ w1, const float* __restrict__ b1, const float* __restrict__ g1,
    const float* __restrict__ be1, const float* __restrict__ m1, const float* __restrict__ v1,
    const float* __restrict__ w2, const float* __restrict__ b2, const float* __restrict__ g2,
    const float* __restrict__ be2, const float* __restrict__ m2, const float* __restrict__ v2,
    const float* __restrict__ w3, const float* __restrict__ b3, const float* __restrict__ g3,
    const float* __restrict__ be3, const float* __restrict__ m3, const float* __restrict__ v3)
{
    int t = threadIdx.x;
    if (t < BATCH) g_progress[t] = 0;
    if (t == 0) g_ctr = 0;
    if (t < 64) {
        float s1 = g1[t] / sqrtf(v1[t] + 1e-5f);
        g_B[t] = (b1[t] - m1[t]) * s1 + be1[t];
        for (int c = 0; c < 3; c++) g_W1t[c * 64 + t] = w1[t * 3 + c] * s1;
        float s2 = g2[t] / sqrtf(v2[t] + 1e-5f);
        g_B[64 + t] = (b2[t] - m2[t]) * s2 + be2[t];
        for (int c = 0; c < 64; c++) g_W2t[c * 64 + t] = w2[t * 64 + c] * s2;
    }
    if (t < 128) {
        float s3 = g3[t] / sqrtf(v3[t] + 1e-5f);
        g_B[128 + t] = (b3[t] - m3[t]) * s3 + be3[t];
        for (int c = 0; c < 64; c++) g_W3t[c * 128 + t] = w3[t * 64 + c] * s3;
    }
}

// ---------------- FPS: Morton-sorted lazy; writer warp off the critical path ----------------
extern __shared__ float fps_sm[];

__device__ __forceinline__ unsigned spread3(unsigned v) {
    v = (v | (v << 4)) & 0x0C3u;
    v = (v | (v << 2)) & 0x249u;
    return v;
}

__global__ __launch_bounds__(1024, 1) void fps_kernel(
    const float* __restrict__ xyz, float* __restrict__ newxyz)
{
    const int b = blockIdx.x;
    const float* P = xyz + (size_t)b * NPTS * 3;
    float* O = newxyz + (size_t)b * NPOINT * 3;
    const int tid = threadIdx.x;
    const int lane = tid & 31, wid = tid >> 5;

    float4* shc = (float4*)fps_sm;          // [8192] coords by original index
    int*    hist  = (int*)(shc + NPTS);     // [4096]
    int*    order = hist + 4096;            // [8192]

    __shared__ unsigned svv[32];            // persistent per-warp max (exact)
    __shared__ unsigned sii[32];            // persistent per-warp tie-min orig idx
    __shared__ float4 s_pick;
    __shared__ int wsums[32];

    for (int i = tid; i < 4096; i += 1024) hist[i] = 0;
    __syncthreads();
    unsigned key[8];
#pragma unroll
    for (int k = 0; k < 8; k++) {
        int p = tid + 1024 * k;
        float x = P[3 * p], y = P[3 * p + 1], z = P[3 * p + 2];
        shc[p] = make_float4(x, y, z, 0.0f);
        int ix = min(15, max(0, (int)(x * 16.0f)));
        int iy = min(15, max(0, (int)(y * 16.0f)));
        int iz = min(15, max(0, (int)(z * 16.0f)));
        key[k] = spread3((unsigned)ix) | (spread3((unsigned)iy) << 1) | (spread3((unsigned)iz) << 2);
        atomicAdd(&hist[key[k]], 1);
    }
    __syncthreads();

    int h0 = hist[4 * tid], h1 = hist[4 * tid + 1], h2 = hist[4 * tid + 2], h3 = hist[4 * tid + 3];
    int tsum = h0 + h1 + h2 + h3;
    int inc = tsum;
#pragma unroll
    for (int off = 1; off < 32; off <<= 1) {
        int n = __shfl_up_sync(FULLM, inc, off);
        if (lane >= off) inc += n;
    }
    if (lane == 31) wsums[wid] = inc;
    __syncthreads();
    if (wid == 0) {
        int s = wsums[lane];
        int i2 = s;
#pragma unroll
        for (int off = 1; off < 32; off <<= 1) {
            int n = __shfl_up_sync(FULLM, i2, off);
            if (lane >= off) i2 += n;
        }
        wsums[lane] = i2 - s;
    }
    __syncthreads();
    {
        int run = wsums[wid] + (inc - tsum);
        hist[4 * tid] = run; run += h0;
        hist[4 * tid + 1] = run; run += h1;
        hist[4 * tid + 2] = run; run += h2;
        hist[4 * tid + 3] = run;
    }
    __syncthreads();

#pragma unroll
    for (int k = 0; k < 8; k++) {
        int pos = atomicAdd(&hist[key[k]], 1);
        order[pos] = tid + 1024 * k;
    }
    __syncthreads();

    float cx = P[0], cy = P[1], cz = P[2];
    if (tid == 0) { O[0] = cx; O[1] = cy; O[2] = cz; }

    int   orig[8];
    float px[8], py[8], pz[8], d[8];
    float bxl = 1e30f, bxh = -1e30f, byl = 1e30f, byh = -1e30f, bzl = 1e30f, bzh = -1e30f;
#pragma unroll
    for (int j = 0; j < 8; j++) {
        int o = order[8 * tid + j];
        orig[j] = o;
        float4 c4 = shc[o];
        float x = c4.x, y = c4.y, z = c4.z;
        px[j] = x; py[j] = y; pz[j] = z;
        bxl = fminf(bxl, x); bxh = fmaxf(bxh, x);
        byl = fminf(byl, y); byh = fmaxf(byh, y);
        bzl = fminf(bzl, z); bzh = fmaxf(bzh, z);
        float dx = __fadd_rn(x, -cx), dy = __fadd_rn(y, -cy), dz = __fadd_rn(z, -cz);
        d[j] = __fadd_rn(__fadd_rn(__fmul_rn(dx, dx), __fmul_rn(dy, dy)), __fmul_rn(dz, dz));
    }
    const float bcx = (bxl + bxh) * 0.5f, bex = (bxh - bxl) * 0.5f;
    const float bcy = (byl + byh) * 0.5f, bey = (byh - byl) * 0.5f;
    const float bcz = (bzl + bzh) * 0.5f, bez = (bzh - bzl) * 0.5f;

    float vmax; unsigned bidx;
    {
        float v = d[0];
#pragma unroll
        for (int j = 1; j < 8; j++) v = fmaxf(v, d[j]);
        unsigned bi = FULLM;
#pragma unroll
        for (int j = 0; j < 8; j++) if (d[j] == v) bi = min(bi, (unsigned)orig[j]);
        vmax = v; bidx = bi;
    }
    {
        unsigned keyv = __float_as_uint(vmax);
        unsigned wm = __reduce_max_sync(FULLM, keyv);
        unsigned cd = (keyv == wm) ? bidx : FULLM;
        unsigned wi = __reduce_min_sync(FULLM, cd);
        if (lane == 0) { svv[wid] = wm; sii[wid] = wi; }
    }

    for (int it = 1; it < NPOINT; ++it) {
        // ---- thread-level conservative skip + exact update ----
        float tx = fmaxf(fabsf(cx - bcx) - bex, 0.0f);
        float ty = fmaxf(fabsf(cy - bcy) - bey, 0.0f);
        float tz = fmaxf(fabsf(cz - bcz) - bez, 0.0f);
        float bound = tx * tx + ty * ty + tz * tz;
        bool upd = bound < vmax * 1.0002f;
        if (upd) {
#pragma unroll
            for (int j = 0; j < 8; j++) {
                float dx = __fadd_rn(px[j], -cx);
                float dy = __fadd_rn(py[j], -cy);
                float dz = __fadd_rn(pz[j], -cz);
                float s = __fadd_rn(__fadd_rn(__fmul_rn(dx, dx), __fmul_rn(dy, dy)),
                                    __fmul_rn(dz, dz));
                d[j] = fminf(d[j], s);
            }
            float v = d[0];
#pragma unroll
            for (int j = 1; j < 8; j++) v = fmaxf(v, d[j]);
            unsigned bi = FULLM;
#pragma unroll
            for (int j = 0; j < 8; j++) if (d[j] == v) bi = min(bi, (unsigned)orig[j]);
            vmax = v; bidx = bi;
        }
        if (__ballot_sync(FULLM, upd)) {
            unsigned keyv = __float_as_uint(vmax);
            unsigned wm = __reduce_max_sync(FULLM, keyv);
            unsigned cd = (keyv == wm) ? bidx : FULLM;
            unsigned wi = __reduce_min_sync(FULLM, cd);
            if (lane == 0) { svv[wid] = wm; sii[wid] = wi; }
        }
        __syncthreads();                         // stores visible to warp 0

        if (wid == 0) {                          // combine + publish pick ONLY
            unsigned k2 = svv[lane];
            unsigned i2 = sii[lane];
            unsigned m2 = __reduce_max_sync(FULLM, k2);
            unsigned c2 = (k2 == m2) ? i2 : FULLM;
            unsigned ci = __reduce_min_sync(FULLM, c2);
            float4 c4 = shc[ci];
            if (lane == 0) s_pick = c4;
        }
        __syncthreads();                         // pick published

        float4 c4 = s_pick;
        cx = c4.x; cy = c4.y; cz = c4.z;

        // writer warp: global O store + progress publish, OFF the serial path.
        // s_pick is stable until the next BAR1 releases (requires warp 31's arrival).
        if (wid == 31 && lane == 0) {
            float* o = O + 3 * it; o[0] = c4.x; o[1] = c4.y; o[2] = c4.z;
            if ((it & 7) == 7) {
                __threadfence();
                *((volatile int*)&g_progress[b]) = it + 1;
            }
        }
    }
}

// ---------------- persistent fused consumer (unchanged) ----------------
extern __shared__ float fus_sm[];

__global__ __launch_bounds__(256) void fused_kernel(
    const float* __restrict__ xyz, const float* __restrict__ newxyz,
    float* __restrict__ out2)
{
    float* W2t   = fus_sm;
    float* W3t   = W2t + 64 * 64;
    float* W1t   = W3t + 64 * 128;
    float* Bsh   = W1t + 192;
    float* stage = Bsh + 256;
    int*   nb    = (int*)(stage + 128 * 8);

    const int tid = threadIdx.x;
    for (int i = tid; i < 64 * 64; i += 256)  W2t[i] = g_W2t[i];
    for (int i = tid; i < 64 * 128; i += 256) W3t[i] = g_W3t[i];
    if (tid < 192) W1t[tid] = g_W1t[tid];
    if (tid < 256) Bsh[tid] = g_B[tid];

    const int w = tid >> 5, lane = tid & 31;
    __shared__ int sh_c;

    for (;;) {
        __syncthreads();
        if (tid == 0) sh_c = (int)atomicAdd(&g_ctr, 1u);
        __syncthreads();
        const int c = sh_c;
        if (c >= NCHUNKS) break;

        const int b  = c & 7;
        const int m0 = (c >> 3) << 3;
        const int m  = m0 + w;

        if (tid == 0) {
            while (*((volatile int*)&g_progress[b]) < m0 + 8) __nanosleep(128);
        }
        __syncthreads();
        __threadfence();

        const float* P = xyz + (size_t)b * NPTS * 3;
        const float* C = newxyz + ((size_t)b * NPOINT + m) * 3;
        const float cx = __ldcg(C), cy = __ldcg(C + 1), cz = __ldcg(C + 2);

        const float R2 = (float)(0.2 * 0.2);
        int* mynb = nb + w * 32;
        int cnt = 0;
        for (int base = 0; base < NPTS && cnt < NSAMPLE; base += 32) {
            int p = base + lane;
            float x = P[3 * p], y = P[3 * p + 1], z = P[3 * p + 2];
            float dx = __fadd_rn(x, -cx), dy = __fadd_rn(y, -cy), dz = __fadd_rn(z, -cz);
            float s = __fadd_rn(__fadd_rn(__fmul_rn(dx, dx), __fmul_rn(dy, dy)), __fmul_rn(dz, dz));
            bool in = (s <= R2);
            unsigned msk = __ballot_sync(FULLM, in);
            int pos = cnt + __popc(msk & ((1u << lane) - 1u));
            if (in && pos < NSAMPLE) mynb[pos] = p;
            cnt += __popc(msk);
        }
        __syncwarp();
        int src = (cnt >= NSAMPLE) ? lane : (lane % cnt);
        int gidx = mynb[src];

        float gx = P[3 * gidx] - cx, gy = P[3 * gidx + 1] - cy, gz = P[3 * gidx + 2] - cz;

        float h1[64];
#pragma unroll
        for (int o = 0; o < 64; o++) h1[o] = fmaf(gx, W1t[o], Bsh[o]);
#pragma unroll
        for (int o = 0; o < 64; o++) h1[o] = fmaf(gy, W1t[64 + o], h1[o]);
#pragma unroll
        for (int o = 0; o < 64; o++) h1[o] = fmaxf(fmaf(gz, W1t[128 + o], h1[o]), 0.0f);

        float h2[64];
#pragma unroll
        for (int o = 0; o < 64; o++) h2[o] = Bsh[64 + o];
#pragma unroll
        for (int cc = 0; cc < 64; cc++) {
            float hc = h1[cc];
            const float4* wr = (const float4*)(W2t + cc * 64);
#pragma unroll
            for (int q = 0; q < 16; q++) {
                float4 wv = wr[q];
                h2[4 * q + 0] = fmaf(hc, wv.x, h2[4 * q + 0]);
                h2[4 * q + 1] = fmaf(hc, wv.y, h2[4 * q + 1]);
                h2[4 * q + 2] = fmaf(hc, wv.z, h2[4 * q + 2]);
                h2[4 * q + 3] = fmaf(hc, wv.w, h2[4 * q + 3]);
            }
        }
#pragma unroll
        for (int o = 0; o < 64; o++) h2[o] = fmaxf(h2[o], 0.0f);

#pragma unroll
        for (int half = 0; half < 2; half++) {
            float acc[64];
#pragma unroll
            for (int o = 0; o < 64; o++) acc[o] = Bsh[128 + half * 64 + o];
#pragma unroll
            for (int cc = 0; cc < 64; cc++) {
                float hc = h2[cc];
                const float4* wr = (const float4*)(W3t + cc * 128 + half * 64);
#pragma unroll
                for (int q = 0; q < 16; q++) {
                    float4 wv = wr[q];
                    acc[4 * q + 0] = fmaf(hc, wv.x, acc[4 * q + 0]);
                    acc[4 * q + 1] = fmaf(hc, wv.y, acc[4 * q + 1]);
                    acc[4 * q + 2] = fmaf(hc, wv.z, acc[4 * q + 2]);
                    acc[4 * q + 3] = fmaf(hc, wv.w, acc[4 * q + 3]);
                }
            }
#pragma unroll
            for (int o = 0; o < 64; o++) acc[o] = fmaxf(acc[o], 0.0f);
#pragma unroll
            for (int off = 16; off >= 1; off >>= 1) {
#pragma unroll
                for (int o = 0; o < 64; o++)
                    acc[o] = fmaxf(acc[o], __shfl_down_sync(FULLM, acc[o], off));
            }
            if (lane == 0) {
#pragma unroll
                for (int o = 0; o < 64; o++) stage[(half * 64 + o) * 8 + w] = acc[o];
            }
        }
        __syncthreads();

        {
            int ch = tid >> 1, part = tid & 1;
            float4 v = ((const float4*)stage)[tid];
            *(float4*)(out2 + ((size_t)(b * 128 + ch)) * NPOINT + m0 + part * 4) = v;
        }
    }
}

// ---------------- launch: prep -> fork {FPS, fused} -> join (R13 topology) ----------------
extern "C" void kernel_launch(void* const* d_in, const int* in_sizes, int n_in,
                              void* d_out, int out_size)
{
    const float* xyz = (const float*)d_in[0];
    const float* w1 = (const float*)d_in[1];  const float* b1 = (const float*)d_in[2];
    const float* g1 = (const float*)d_in[3];  const float* be1 = (const float*)d_in[4];
    const float* m1 = (const float*)d_in[5];  const float* v1 = (const float*)d_in[6];
    const float* w2 = (const float*)d_in[7];  const float* b2 = (const float*)d_in[8];
    const float* g2 = (const float*)d_in[9];  const float* be2 = (const float*)d_in[10];
    const float* m2 = (const float*)d_in[11]; const float* v2 = (const float*)d_in[12];
    const float* w3 = (const float*)d_in[13]; const float* b3 = (const float*)d_in[14];
    const float* g3 = (const float*)d_in[15]; const float* be3 = (const float*)d_in[16];
    const float* m3 = (const float*)d_in[17]; const float* v3 = (const float*)d_in[18];

    float* out = (float*)d_out;
    float* newxyz = out;
    float* out2 = out + (size_t)BATCH * NPOINT * 3;

    static cudaStream_t s_aux = nullptr;
    static cudaEvent_t e_fork = nullptr, e_join = nullptr;
    if (s_aux == nullptr) {
        cudaStreamCreateWithFlags(&s_aux, cudaStreamNonBlocking);
        cudaEventCreateWithFlags(&e_fork, cudaEventDisableTiming);
        cudaEventCreateWithFlags(&e_join, cudaEventDisableTiming);
    }

    const int FPS_SMEM = NPTS * 16 + 4096 * 4 + NPTS * 4;   // 180224
    cudaFuncSetAttribute(fps_kernel, cudaFuncAttributeMaxDynamicSharedMemorySize, FPS_SMEM);
    cudaFuncSetAttribute(fused_kernel, cudaFuncAttributeMaxDynamicSharedMemorySize, 57344);

    prep_kernel<<<1, 128>>>(w1, b1, g1, be1, m1, v1,
                            w2, b2, g2, be2, m2, v2,
                            w3, b3, g3, be3, m3, v3);

    cudaEventRecord(e_fork, 0);
    cudaStreamWaitEvent(s_aux, e_fork, 0);

    fps_kernel<<<BATCH, 1024, FPS_SMEM>>>(xyz, newxyz);
    fused_kernel<<<FUSED_BLOCKS, 256, 56064, s_aux>>>(xyz, newxyz, out2);

    cudaEventRecord(e_join, s_aux);
    cudaStreamWaitEvent(0, e_join, 0);
    (void)in_sizes; (void)n_in; (void)out_size;
}